// round 6
// baseline (speedup 1.0000x reference)
#include <cuda_runtime.h>
#include <cuda_bf16.h>
#include <math.h>
#include <stdint.h>

#define BOX_P 32
#define PATCH_ELEMS (BOX_P * BOX_P)   // 1024
#define NP 4                          // patches per CTA (one per warp)
#define THREADS (NP * 32)
#define ROW_F 40                      // smem row: 40 floats = 160B (aligned superset)
#define ROW_BYTES (ROW_F * 4)
#define TILE_BYTES (BOX_P * ROW_BYTES)   // 5120 B per image tile
#define EPSF 1e-6f

__global__ void lp_zero_out(float* out) {
    if (threadIdx.x == 0) out[0] = 0.0f;
}

__device__ __forceinline__ uint32_t smem_u32(const void* p) {
    return (uint32_t)__cvta_generic_to_shared(p);
}

__global__ __launch_bounds__(THREADS)
void lp_pearson_bulk_kernel(const float* __restrict__ pred,
                            const float* __restrict__ gt,
                            const int*   __restrict__ x0,
                            const int*   __restrict__ y0,
                            float* __restrict__ out,
                            int n_corr, int W)
{
    __shared__ __align__(128) float tiles[NP][2][BOX_P * ROW_F]; // 40960 B
    __shared__ __align__(8)  unsigned long long mbar[NP];

    const int warp = threadIdx.x >> 5;
    const int lane = threadIdx.x & 31;
    const int b = blockIdx.x * NP + warp;
    const bool valid = (b < n_corr);

    if (valid) {
        if (lane == 0) {
            uint32_t mb = smem_u32(&mbar[warp]);
            asm volatile("mbarrier.init.shared.b64 [%0], 1;" :: "r"(mb) : "memory");
            asm volatile("fence.proxy.async.shared::cta;" ::: "memory");
        }
        __syncwarp();

        const int X = x0[b];
        const int Y = y0[b];
        int Y4 = Y & ~3;                       // 16B-aligned source start
        if (Y4 > W - ROW_F) Y4 = W - ROW_F;    // clamp: never read past row/image end
        const int off = Y - Y4;                // 0..8, data starts at smem col `off`

        const uint32_t mb = smem_u32(&mbar[warp]);
        if (lane == 0) {
            asm volatile("mbarrier.arrive.expect_tx.shared.b64 _, [%0], %1;"
                         :: "r"(mb), "r"(2u * TILE_BYTES) : "memory");
        }

        // Each lane copies row `lane` of both images: 160B aligned bulk copies
        // through the async (TMA/UBLKCP) engine -> deep in-flight queue,
        // bypassing the per-SM L1tex wavefront FIFO.
        {
            const size_t goff = ((size_t)(X + lane)) * W + Y4;
            const float* gsrc_p = pred + goff;
            const float* gsrc_g = gt   + goff;
            const uint32_t dst_p = smem_u32(&tiles[warp][0][lane * ROW_F]);
            const uint32_t dst_g = smem_u32(&tiles[warp][1][lane * ROW_F]);
            asm volatile(
                "cp.async.bulk.shared::cta.global.mbarrier::complete_tx::bytes "
                "[%0], [%1], %2, [%3];"
                :: "r"(dst_p), "l"(gsrc_p), "n"(ROW_BYTES), "r"(mb) : "memory");
            asm volatile(
                "cp.async.bulk.shared::cta.global.mbarrier::complete_tx::bytes "
                "[%0], [%1], %2, [%3];"
                :: "r"(dst_g), "l"(gsrc_g), "n"(ROW_BYTES), "r"(mb) : "memory");
        }

        // Wait (parity 0, single use)
        {
            uint32_t done;
            asm volatile(
                "{\n\t.reg .pred p;\n\t"
                "mbarrier.try_wait.parity.shared.b64 p, [%1], 0;\n\t"
                "selp.b32 %0, 1, 0, p;\n\t}"
                : "=r"(done) : "r"(mb) : "memory");
            while (!done) {
                asm volatile(
                    "{\n\t.reg .pred p;\n\t"
                    "mbarrier.try_wait.parity.shared.b64 p, [%1], 0, 0x989680;\n\t"
                    "selp.b32 %0, 1, 0, p;\n\t}"
                    : "=r"(done) : "r"(mb) : "memory");
            }
        }

        // Reduce: lane owns column `lane`; walk 32 rows of each tile.
        // addr = row*160 + (off+lane)*4 -> 32 consecutive banks, conflict-free.
        float sp = 0.f, sg = 0.f, spp = 0.f, sgg = 0.f, spg = 0.f;
        const float* tp = &tiles[warp][0][off + lane];
        const float* tg = &tiles[warp][1][off + lane];
        #pragma unroll
        for (int r = 0; r < BOX_P; r++) {
            const float p = tp[r * ROW_F];
            const float g = tg[r * ROW_F];
            sp  += p;
            sg  += g;
            spp += p * p;
            sgg += g * g;
            spg += p * g;
        }

        #pragma unroll
        for (int o = 16; o > 0; o >>= 1) {
            sp  += __shfl_down_sync(0xFFFFFFFFu, sp,  o);
            sg  += __shfl_down_sync(0xFFFFFFFFu, sg,  o);
            spp += __shfl_down_sync(0xFFFFFFFFu, spp, o);
            sgg += __shfl_down_sync(0xFFFFFFFFu, sgg, o);
            spg += __shfl_down_sync(0xFFFFFFFFu, spg, o);
        }

        if (lane == 0) {
            const float P    = (float)PATCH_ELEMS;
            const float invP = 1.0f / P;
            const float mp = sp * invP;
            const float mg = sg * invP;
            // unbiased (ddof=1) variance, matching jnp.std(ddof=1)
            const float varp = (spp - sp * mp) / (P - 1.0f);
            const float varg = (sgg - sg * mg) / (P - 1.0f);
            const float sdp = sqrtf(fmaxf(varp, 0.f)) + EPSF;
            const float sdg = sqrtf(fmaxf(varg, 0.f)) + EPSF;
            const float cov = spg - sp * mg;   // = Spg - Sp*Sg/P
            const float co  = cov / (P * sdp * sdg);
            atomicAdd(out, (1.0f - co) / (float)n_corr);
        }
    }
}

extern "C" void kernel_launch(void* const* d_in, const int* in_sizes, int n_in,
                              void* d_out, int out_size)
{
    const float* pred = (const float*)d_in[0];
    const float* gt   = (const float*)d_in[1];
    const int*   x0   = (const int*)d_in[2];
    const int*   y0   = (const int*)d_in[3];
    float* out = (float*)d_out;

    const int n_corr = in_sizes[2];

    // Derive W from the (square, C=1) image element count.
    int W = 1;
    while ((long long)W * W < (long long)in_sizes[0]) W <<= 1;

    const int grid = (n_corr + NP - 1) / NP;
    lp_zero_out<<<1, 32>>>(out);
    lp_pearson_bulk_kernel<<<grid, THREADS>>>(pred, gt, x0, y0, out, n_corr, W);
}